// round 7
// baseline (speedup 1.0000x reference)
#include <cuda_runtime.h>
#include <stdint.h>

#define USER_N 100000
#define ITEM_N 50000
#define TAG_CNT 20000
#define NN 150000            // USER+ITEM
#define MM 70000             // ITEM+TAG
#define D 64
#define EADJ 2000000
#define ETAG 1000000
#define ESOC 1000000
#define ETOT (EADJ + ETAG + ESOC)

// ---------------- scratch (device globals; no allocations allowed) ----------
__device__ float g_lat [(size_t)NN * D];
__device__ float g_tagl[(size_t)MM * D];
__device__ float g_tem [(size_t)NN * D];
__device__ float g_tgr [(size_t)MM * D];
__device__ float g_soc [(size_t)USER_N * D];
__device__ float g_eff_adj[EADJ];
__device__ float g_eff_tag[ETAG];
__device__ float g_eff_soc[ESOC];

// ---------------- JAX threefry-2x32 (exact) ---------------------------------
__host__ __device__ __forceinline__ void tf2x32(uint32_t k0, uint32_t k1,
                                                uint32_t x0, uint32_t x1,
                                                uint32_t* o0, uint32_t* o1) {
    uint32_t k2 = k0 ^ k1 ^ 0x1BD11BDAu;
    x0 += k0; x1 += k1;
#define TF_RND(r) { x0 += x1; x1 = (x1 << (r)) | (x1 >> (32 - (r))); x1 ^= x0; }
    TF_RND(13) TF_RND(15) TF_RND(26) TF_RND(6)
    x0 += k1; x1 += k2 + 1u;
    TF_RND(17) TF_RND(29) TF_RND(16) TF_RND(24)
    x0 += k2; x1 += k0 + 2u;
    TF_RND(13) TF_RND(15) TF_RND(26) TF_RND(6)
    x0 += k0; x1 += k1 + 3u;
    TF_RND(17) TF_RND(29) TF_RND(16) TF_RND(24)
    x0 += k1; x1 += k2 + 4u;
    TF_RND(13) TF_RND(15) TF_RND(26) TF_RND(6)
    x0 += k2; x1 += k0 + 5u;
#undef TF_RND
    *o0 = x0; *o1 = x1;
}

// partitionable threefry random_bits (32-bit): bits[i] = o0 ^ o1 of count (0, i)
__device__ __forceinline__ float tf_mask_times_inv(uint32_t k0, uint32_t k1, uint32_t i) {
    uint32_t o0, o1;
    tf2x32(k0, k1, 0u, i, &o0, &o1);
    uint32_t bits = o0 ^ o1;
    float u = __uint_as_float((bits >> 9) | 0x3f800000u) - 1.0f;
    const float inv = (float)(1.0 / 0.9);           // f32(1.0/KEEP)
    return floorf(u + 0.9f) * inv;                  // 0 or 1.11111116
}

// ---------------- fused dropout mask pass (one thread per edge) -------------
__global__ void mask_all(const float* __restrict__ adj_v,
                         const float* __restrict__ tag_v,
                         const float* __restrict__ soc_v,
                         uint32_t a0, uint32_t a1,
                         uint32_t t0, uint32_t t1,
                         uint32_t s0, uint32_t s1) {
    int t = blockIdx.x * blockDim.x + threadIdx.x;
    if (t < EADJ) {
        g_eff_adj[t] = adj_v[t] * tf_mask_times_inv(a0, a1, (uint32_t)t);
    } else if (t < EADJ + ETAG) {
        int e = t - EADJ;
        g_eff_tag[e] = tag_v[e] * tf_mask_times_inv(t0, t1, (uint32_t)e);
    } else if (t < ETOT) {
        int e = t - (EADJ + ETAG);
        g_eff_soc[e] = soc_v[e] * tf_mask_times_inv(s0, s1, (uint32_t)e);
    }
}

// ---------------- zero scatter targets ---------------------------------------
__global__ void zero_kernel() {
    int t = blockIdx.x * blockDim.x + threadIdx.x;  // float4 index
    const float4 z = {0.f, 0.f, 0.f, 0.f};
    if (t < NN * (D / 4))      ((float4*)g_tem)[t] = z;
    if (t < MM * (D / 4))      ((float4*)g_tgr)[t] = z;
    if (t < USER_N * (D / 4))  ((float4*)g_soc)[t] = z;
}

// ---------------- SpMM: 16 threads per edge, float4, red.v4 scatter ----------
__device__ __forceinline__ void red_add_v4(float* dst, float4 p) {
    asm volatile("red.global.add.v4.f32 [%0], {%1,%2,%3,%4};"
                 :: "l"(dst), "f"(p.x), "f"(p.y), "f"(p.z), "f"(p.w) : "memory");
}

__global__ void spmm_adj(const int* __restrict__ rows, const int* __restrict__ cols) {
    int t = blockIdx.x * blockDim.x + threadIdx.x;
    int e = t >> 4;
    if (e >= EADJ) return;
    float v = g_eff_adj[e];
    if (v == 0.0f) return;                 // whole 16-lane group exits together
    int lane = t & 15;
    int r = rows[e], c = cols[e];
    float4 x = *(const float4*)(g_lat + (size_t)c * D + lane * 4);
    float4 p = {x.x * v, x.y * v, x.z * v, x.w * v};
    red_add_v4(g_tem + (size_t)r * D + lane * 4, p);
}

__global__ void spmm_tag(const int* __restrict__ rows, const int* __restrict__ cols) {
    int t = blockIdx.x * blockDim.x + threadIdx.x;
    int e = t >> 4;
    if (e >= ETAG) return;
    float v = g_eff_tag[e];
    if (v == 0.0f) return;
    int lane = t & 15;
    int r = rows[e], c = cols[e];
    // tg_in = concat(lat[USER:], tag_lat[ITEM:]) : c<ITEM -> lat[USER+c], else tag_lat[c]
    const float* src = (c < ITEM_N) ? (g_lat + (size_t)(USER_N + c) * D)
                                    : (g_tagl + (size_t)c * D);
    float4 x = *(const float4*)(src + lane * 4);
    float4 p = {x.x * v, x.y * v, x.z * v, x.w * v};
    red_add_v4(g_tgr + (size_t)r * D + lane * 4, p);
}

__global__ void spmm_soc(const int* __restrict__ rows, const int* __restrict__ cols) {
    int t = blockIdx.x * blockDim.x + threadIdx.x;
    int e = t >> 4;
    if (e >= ESOC) return;
    float v = g_eff_soc[e];
    if (v == 0.0f) return;
    int lane = t & 15;
    int r = rows[e], c = cols[e];
    float4 x = *(const float4*)(g_lat + (size_t)c * D + lane * 4);
    float4 p = {x.x * v, x.y * v, x.z * v, x.w * v};
    red_add_v4(g_soc + (size_t)r * D + lane * 4, p);
}

// ---------------- epilogues --------------------------------------------------
__device__ __forceinline__ float lrelu(float h) { return h >= 0.0f ? h : 0.5f * h; }
__device__ __forceinline__ float4 lrelu4(float4 h) {
    return make_float4(lrelu(h.x), lrelu(h.y), lrelu(h.z), lrelu(h.w));
}

// lat = concat(lrelu(tem[:USER]) + lrelu(soc), lrelu(tem[USER:]) + lrelu(tg[:ITEM])); acc += lat
__global__ void combine_kernel(float4* __restrict__ out) {
    int t = blockIdx.x * blockDim.x + threadIdx.x;   // float4 index over NN*16
    if (t >= NN * (D / 4)) return;
    int n = t >> 4;
    float4 a = lrelu4(((const float4*)g_tem)[t]);
    float4 b;
    if (n < USER_N) b = ((const float4*)g_soc)[t];
    else            b = ((const float4*)g_tgr)[t - USER_N * (D / 4)];
    b = lrelu4(b);
    float4 l = make_float4(a.x + b.x, a.y + b.y, a.z + b.z, a.w + b.w);
    ((float4*)g_lat)[t] = l;
    float4 o = out[t];
    out[t] = make_float4(o.x + l.x, o.y + l.y, o.z + l.z, o.w + l.w);
}

// tag_lat = lrelu(tg_raw)
__global__ void tagupd_kernel() {
    int t = blockIdx.x * blockDim.x + threadIdx.x;
    if (t >= MM * (D / 4)) return;
    ((float4*)g_tagl)[t] = lrelu4(((const float4*)g_tgr)[t]);
}

// lat = concat(u, i); tag_lat = concat(i, tagE); acc(out) = lat
__global__ void init_kernel(const float4* __restrict__ uE, const float4* __restrict__ iE,
                            const float4* __restrict__ tE, float4* __restrict__ out) {
    int t = blockIdx.x * blockDim.x + threadIdx.x;
    if (t < NN * (D / 4)) {
        int n = t >> 4;
        float4 v = (n < USER_N) ? uE[t] : iE[t - USER_N * (D / 4)];
        ((float4*)g_lat)[t] = v;
        out[t] = v;
    }
    if (t < MM * (D / 4)) {
        int m = t >> 4;
        float4 w = (m < ITEM_N) ? iE[t] : tE[t - ITEM_N * (D / 4)];
        ((float4*)g_tagl)[t] = w;
    }
}

// ---------------- launch ------------------------------------------------------
static inline int cdiv(long long a, int b) { return (int)((a + b - 1) / b); }

extern "C" void kernel_launch(void* const* d_in, const int* in_sizes, int n_in,
                              void* d_out, int out_size) {
    const float* uE    = (const float*)d_in[0];
    const float* iE    = (const float*)d_in[1];
    const float* tE    = (const float*)d_in[2];
    const int*   adj_r = (const int*)d_in[3];
    const int*   adj_c = (const int*)d_in[4];
    const float* adj_v = (const float*)d_in[5];
    const int*   tag_r = (const int*)d_in[6];
    const int*   tag_c = (const int*)d_in[7];
    const float* tag_v = (const float*)d_in[8];
    const int*   soc_r = (const int*)d_in[9];
    const int*   soc_c = (const int*)d_in[10];
    const float* soc_v = (const float*)d_in[11];
    float* out = (float*)d_out;

    const int B = 256;
    const int n4_max = NN * (D / 4);          // 2.4M float4 elems (largest)

    init_kernel<<<cdiv(n4_max, B), B>>>((const float4*)uE, (const float4*)iE,
                                        (const float4*)tE, (float4*)out);

    for (int layer = 0; layer < 2; layer++) {
        // fold_in(key(42), 3*layer + j) computed on host, bit-exact threefry
        uint32_t kk[6];
        for (int j = 0; j < 3; j++) {
            uint32_t o0, o1;
            tf2x32(0u, 42u, 0u, (uint32_t)(3 * layer + j), &o0, &o1);
            kk[2 * j] = o0; kk[2 * j + 1] = o1;
        }

        mask_all<<<cdiv(ETOT, B), B>>>(adj_v, tag_v, soc_v,
                                       kk[0], kk[1], kk[2], kk[3], kk[4], kk[5]);

        zero_kernel<<<cdiv(n4_max, B), B>>>();

        spmm_adj<<<cdiv((long long)EADJ * 16, B), B>>>(adj_r, adj_c);
        spmm_tag<<<cdiv((long long)ETAG * 16, B), B>>>(tag_r, tag_c);
        spmm_soc<<<cdiv((long long)ESOC * 16, B), B>>>(soc_r, soc_c);

        combine_kernel<<<cdiv(n4_max, B), B>>>((float4*)out);
        tagupd_kernel<<<cdiv(MM * (D / 4), B), B>>>();
    }
}

// round 15
// speedup vs baseline: 1.1694x; 1.1694x over previous
#include <cuda_runtime.h>
#include <stdint.h>

#define USER_N 100000
#define ITEM_N 50000
#define NN 150000            // USER+ITEM
#define MM 70000             // ITEM+TAG
#define D 64
#define EADJ 2000000
#define ETAG 1000000
#define ESOC 1000000
#define ETOT (EADJ + ETAG + ESOC)

// ---------------- scratch (device globals; no allocations allowed) ----------
__device__ float g_lat [(size_t)NN * D];
__device__ float g_tagl[(size_t)MM * D];
__device__ float g_tem [(size_t)NN * D];
__device__ float g_tgr [(size_t)MM * D];
__device__ float g_soc [(size_t)USER_N * D];
// packed surviving-edge records: {v, row, ptr_lo, ptr_hi}
__device__ float4 g_pk_adj[EADJ];
__device__ float4 g_pk_tag[ETAG];
__device__ float4 g_pk_soc[ESOC];
__device__ int    g_cnt[3];

// ---------------- JAX threefry-2x32 (exact) ---------------------------------
__host__ __device__ __forceinline__ void tf2x32(uint32_t k0, uint32_t k1,
                                                uint32_t x0, uint32_t x1,
                                                uint32_t* o0, uint32_t* o1) {
    uint32_t k2 = k0 ^ k1 ^ 0x1BD11BDAu;
    x0 += k0; x1 += k1;
#define TF_RND(r) { x0 += x1; x1 = (x1 << (r)) | (x1 >> (32 - (r))); x1 ^= x0; }
    TF_RND(13) TF_RND(15) TF_RND(26) TF_RND(6)
    x0 += k1; x1 += k2 + 1u;
    TF_RND(17) TF_RND(29) TF_RND(16) TF_RND(24)
    x0 += k2; x1 += k0 + 2u;
    TF_RND(13) TF_RND(15) TF_RND(26) TF_RND(6)
    x0 += k0; x1 += k1 + 3u;
    TF_RND(17) TF_RND(29) TF_RND(16) TF_RND(24)
    x0 += k1; x1 += k2 + 4u;
    TF_RND(13) TF_RND(15) TF_RND(26) TF_RND(6)
    x0 += k2; x1 += k0 + 5u;
#undef TF_RND
    *o0 = x0; *o1 = x1;
}

// partitionable threefry random_bits (32-bit): bits[i] = o0 ^ o1 of count (0, i)
__device__ __forceinline__ float tf_mask_times_inv(uint32_t k0, uint32_t k1, uint32_t i) {
    uint32_t o0, o1;
    tf2x32(k0, k1, 0u, i, &o0, &o1);
    uint32_t bits = o0 ^ o1;
    float u = __uint_as_float((bits >> 9) | 0x3f800000u) - 1.0f;
    const float inv = (float)(1.0 / 0.9);           // f32(1.0/KEEP)
    return floorf(u + 0.9f) * inv;                  // 0 or 1.11111116
}

// ---------------- zero scatter targets + compaction counters ----------------
__global__ void zero_kernel() {
    int t = blockIdx.x * blockDim.x + threadIdx.x;  // float4 index
    const float4 z = {0.f, 0.f, 0.f, 0.f};
    if (t < NN * (D / 4))      ((float4*)g_tem)[t] = z;
    if (t < MM * (D / 4))      ((float4*)g_tgr)[t] = z;
    if (t < USER_N * (D / 4))  ((float4*)g_soc)[t] = z;
    if (t < 3)                 g_cnt[t] = 0;
}

// ---------------- fused dropout + pack + compact (one thread per edge) ------
// Emits 16B records {v*mask*inv, row, resolved 64-bit gather ptr} for kept
// edges only, warp-aggregated atomic compaction. Grid covers exactly ETOT.
__global__ void mask_compact(const float* __restrict__ adj_v, const int* __restrict__ adj_r, const int* __restrict__ adj_c,
                             const float* __restrict__ tag_v, const int* __restrict__ tag_r, const int* __restrict__ tag_c,
                             const float* __restrict__ soc_v, const int* __restrict__ soc_r, const int* __restrict__ soc_c,
                             uint32_t a0, uint32_t a1,
                             uint32_t t0, uint32_t t1,
                             uint32_t s0, uint32_t s1) {
    int t = blockIdx.x * blockDim.x + threadIdx.x;   // always < ETOT (grid exact)
    int seg, e; uint32_t k0, k1;
    const float* pv; const int* pr; const int* pc; float4* pk;
    if (t < EADJ) {
        seg = 0; e = t; k0 = a0; k1 = a1; pv = adj_v; pr = adj_r; pc = adj_c; pk = g_pk_adj;
    } else if (t < EADJ + ETAG) {
        seg = 1; e = t - EADJ; k0 = t0; k1 = t1; pv = tag_v; pr = tag_r; pc = tag_c; pk = g_pk_tag;
    } else {
        seg = 2; e = t - (EADJ + ETAG); k0 = s0; k1 = s1; pv = soc_v; pr = soc_r; pc = soc_c; pk = g_pk_soc;
    }
    float w = tf_mask_times_inv(k0, k1, (uint32_t)e);
    bool keep = (w != 0.0f);

    unsigned grp = __match_any_sync(0xffffffffu, seg);      // handles segment-straddling warps
    unsigned km  = __ballot_sync(0xffffffffu, keep) & grp;  // kept lanes of my segment group
    if (keep) {
        int lanei  = threadIdx.x & 31;
        int leader = __ffs(km) - 1;
        int base;
        if (lanei == leader) base = atomicAdd(&g_cnt[seg], __popc(km));
        base = __shfl_sync(km, base, leader);
        int rank = __popc(km & ((1u << lanei) - 1u));

        float v = pv[e] * w;
        int r = pr[e];
        int c = pc[e];
        const float* src;
        if (seg == 1) {
            // tg_in = concat(lat[USER:], tag_lat[ITEM:])
            src = (c < ITEM_N) ? (g_lat + (size_t)(USER_N + c) * D)
                               : (g_tagl + (size_t)c * D);
        } else {
            src = g_lat + (size_t)c * D;
        }
        unsigned long long p = (unsigned long long)(uintptr_t)src;
        pk[base + rank] = make_float4(v, __int_as_float(r),
                                      __uint_as_float((unsigned)p),
                                      __uint_as_float((unsigned)(p >> 32)));
    }
}

// ---------------- SpMM: 16 lanes/edge, 4 edges per slot (MLP=4) -------------
__device__ __forceinline__ void red_add_v4(float* dst, float4 p) {
    asm volatile("red.global.add.v4.f32 [%0], {%1,%2,%3,%4};"
                 :: "l"(dst), "f"(p.x), "f"(p.y), "f"(p.z), "f"(p.w) : "memory");
}

template<int MODE>   // 0: adj->tem, 1: tag->tgr, 2: soc->soc
__global__ void spmm_k() {
    const float4* pk = (MODE == 0) ? g_pk_adj : (MODE == 1) ? g_pk_tag : g_pk_soc;
    float*        dst = (MODE == 0) ? g_tem   : (MODE == 1) ? g_tgr   : g_soc;
    int cnt = g_cnt[MODE];
    int t    = blockIdx.x * blockDim.x + threadIdx.x;
    int lane = t & 15;
    int e0   = (t >> 4) * 4;
    if (e0 >= cnt) return;
    int m = cnt - e0; if (m > 4) m = 4;

    float4 rec[4];
    #pragma unroll
    for (int i = 0; i < 4; i++) if (i < m) rec[i] = pk[e0 + i];

    float4 x[4];
    #pragma unroll
    for (int i = 0; i < 4; i++) if (i < m) {
        unsigned long long p = ((unsigned long long)__float_as_uint(rec[i].w) << 32)
                             | (unsigned long long)__float_as_uint(rec[i].z);
        x[i] = *((const float4*)p + lane);
    }

    #pragma unroll
    for (int i = 0; i < 4; i++) if (i < m) {
        float v = rec[i].x;
        int   r = __float_as_int(rec[i].y);
        float4 pr = {x[i].x * v, x[i].y * v, x[i].z * v, x[i].w * v};
        red_add_v4(dst + (size_t)r * D + lane * 4, pr);
    }
}

// ---------------- epilogues --------------------------------------------------
__device__ __forceinline__ float lrelu(float h) { return h >= 0.0f ? h : 0.5f * h; }
__device__ __forceinline__ float4 lrelu4(float4 h) {
    return make_float4(lrelu(h.x), lrelu(h.y), lrelu(h.z), lrelu(h.w));
}

// lat = concat(lrelu(tem[:USER])+lrelu(soc), lrelu(tem[USER:])+lrelu(tg[:ITEM])); acc += lat
// also: tag_lat = lrelu(tg_raw)   (merged)
__global__ void combine_tag_kernel(float4* __restrict__ out) {
    int t = blockIdx.x * blockDim.x + threadIdx.x;   // float4 index over NN*16
    if (t < NN * (D / 4)) {
        int n = t >> 4;
        float4 a = lrelu4(((const float4*)g_tem)[t]);
        float4 b;
        if (n < USER_N) b = ((const float4*)g_soc)[t];
        else            b = ((const float4*)g_tgr)[t - USER_N * (D / 4)];
        b = lrelu4(b);
        float4 l = make_float4(a.x + b.x, a.y + b.y, a.z + b.z, a.w + b.w);
        ((float4*)g_lat)[t] = l;
        float4 o = out[t];
        out[t] = make_float4(o.x + l.x, o.y + l.y, o.z + l.z, o.w + l.w);
    }
    if (t < MM * (D / 4)) {
        ((float4*)g_tagl)[t] = lrelu4(((const float4*)g_tgr)[t]);
    }
}

// lat = concat(u, i); tag_lat = concat(i, tagE); acc(out) = lat
__global__ void init_kernel(const float4* __restrict__ uE, const float4* __restrict__ iE,
                            const float4* __restrict__ tE, float4* __restrict__ out) {
    int t = blockIdx.x * blockDim.x + threadIdx.x;
    if (t < NN * (D / 4)) {
        int n = t >> 4;
        float4 v = (n < USER_N) ? uE[t] : iE[t - USER_N * (D / 4)];
        ((float4*)g_lat)[t] = v;
        out[t] = v;
    }
    if (t < MM * (D / 4)) {
        int m = t >> 4;
        float4 w = (m < ITEM_N) ? iE[t] : tE[t - ITEM_N * (D / 4)];
        ((float4*)g_tagl)[t] = w;
    }
}

// ---------------- launch ------------------------------------------------------
static inline int cdiv(long long a, int b) { return (int)((a + b - 1) / b); }

extern "C" void kernel_launch(void* const* d_in, const int* in_sizes, int n_in,
                              void* d_out, int out_size) {
    const float* uE    = (const float*)d_in[0];
    const float* iE    = (const float*)d_in[1];
    const float* tE    = (const float*)d_in[2];
    const int*   adj_r = (const int*)d_in[3];
    const int*   adj_c = (const int*)d_in[4];
    const float* adj_v = (const float*)d_in[5];
    const int*   tag_r = (const int*)d_in[6];
    const int*   tag_c = (const int*)d_in[7];
    const float* tag_v = (const float*)d_in[8];
    const int*   soc_r = (const int*)d_in[9];
    const int*   soc_c = (const int*)d_in[10];
    const float* soc_v = (const float*)d_in[11];
    float* out = (float*)d_out;

    const int B = 256;
    const int n4_max = NN * (D / 4);          // 2.4M float4 elems (largest)

    init_kernel<<<cdiv(n4_max, B), B>>>((const float4*)uE, (const float4*)iE,
                                        (const float4*)tE, (float4*)out);

    for (int layer = 0; layer < 2; layer++) {
        // fold_in(key(42), 3*layer + j) computed on host, bit-exact threefry
        uint32_t kk[6];
        for (int j = 0; j < 3; j++) {
            uint32_t o0, o1;
            tf2x32(0u, 42u, 0u, (uint32_t)(3 * layer + j), &o0, &o1);
            kk[2 * j] = o0; kk[2 * j + 1] = o1;
        }

        zero_kernel<<<cdiv(n4_max, B), B>>>();   // zeroes targets + g_cnt

        mask_compact<<<ETOT / B, B>>>(adj_v, adj_r, adj_c,
                                      tag_v, tag_r, tag_c,
                                      soc_v, soc_r, soc_c,
                                      kk[0], kk[1], kk[2], kk[3], kk[4], kk[5]);

        // slots cover full edge count (grid fixed at capture; excess exits on cnt)
        spmm_k<0><<<cdiv((long long)cdiv(EADJ, 4) * 16, B), B>>>();
        spmm_k<1><<<cdiv((long long)cdiv(ETAG, 4) * 16, B), B>>>();
        spmm_k<2><<<cdiv((long long)cdiv(ESOC, 4) * 16, B), B>>>();

        combine_tag_kernel<<<cdiv(n4_max, B), B>>>((float4*)out);
    }
}